// round 16
// baseline (speedup 1.0000x reference)
#include <cuda_runtime.h>
#include <cuda_fp16.h>

#define NN 10000
#define EE 640000
#define FIN 128
#define NH 8
#define FOUT 16
#define NEG 0.2f
#define EPSF 1e-16f

#define GEMM_BLOCKS 625          // 10000 / 16
#define COUNT_BLOCKS ((EE + 127) / 128)

// ---------------- scratch (static device memory; zero-initialized at load) -----
__device__ __half g_proj16[NN * FIN];   // 2.56 MB, fp16 proj for aggregation
__device__ float g_ssrc[NN * NH];
__device__ float g_stgt[NN * NH];
__device__ int   g_count[NN];           // zeroed at end of k_agg
__device__ int   g_offs[NN + 1];
__device__ int   g_cursor[NN];
__device__ int   g_ssorted[EE];         // src id per CSR slot
__device__ unsigned g_maxsrc[NH];       // zeroed at end of k_agg
__device__ unsigned g_maxtgt[NH];
__device__ float g_C[NH];               // softmax shift constants

__device__ __forceinline__ unsigned f2u_ord(float f) {
    unsigned u = __float_as_uint(f);
    return (u & 0x80000000u) ? ~u : (u | 0x80000000u);
}
__device__ __forceinline__ float u2f_ord(unsigned u) {
    return __uint_as_float((u & 0x80000000u) ? (u ^ 0x80000000u) : ~u);
}

// ---------------- fused: proj+skip GEMM (+bias,+scores)  ||  edge counting -----
// GEMM blocks: 128 threads, 16 nodes; thread t owns output col t of BOTH mats.
// W staged in fp16 smem, k-split in 2 halves of 64. Row pad to 68 halves
// (34 words ≡ 2 mod 32 -> LDS.64 conflict-free).
__global__ void __launch_bounds__(128) k_fused(
    const float* __restrict__ x, const float* __restrict__ Wp,
    const float* __restrict__ Ws, const float* __restrict__ bias,
    const float* __restrict__ sw_src, const float* __restrict__ sw_tgt,
    const int* __restrict__ edges, float* __restrict__ out)
{
    __shared__ float4 xs4[16][32];          // 8 KB
    __shared__ __half wsm[2][128][68];      // 34.8 KB
    int t = threadIdx.x;

    if (blockIdx.x >= GEMM_BLOCKS) {
        int e = (blockIdx.x - GEMM_BLOCKS) * 128 + t;
        if (e < EE) atomicAdd(&g_count[edges[EE + e]], 1);
        return;
    }

    int node0 = blockIdx.x * 16;

    const float4* xg = (const float4*)(x + node0 * FIN);
    for (int i = t; i < 512; i += 128) xs4[i >> 5][i & 31] = xg[i];

    float accP[16], accS[16];
#pragma unroll
    for (int n = 0; n < 16; n++) { accP[n] = 0.0f; accS[n] = 0.0f; }

    for (int kh = 0; kh < 2; kh++) {
        __syncthreads();                    // also orders x-tile on first pass
        for (int j = t; j < 2048; j += 128) {
            int col = j >> 4;               // 16 float4 per col
            int kk = (j & 15) << 2;         // half-index 0..60
            float4 wv = *(const float4*)(Wp + col * FIN + kh * 64 + kk);
            float4 sv = *(const float4*)(Ws + col * FIN + kh * 64 + kk);
            __half2* dp = (__half2*)&wsm[0][col][kk];
            dp[0] = __floats2half2_rn(wv.x, wv.y);
            dp[1] = __floats2half2_rn(wv.z, wv.w);
            __half2* ds = (__half2*)&wsm[1][col][kk];
            ds[0] = __floats2half2_rn(sv.x, sv.y);
            ds[1] = __floats2half2_rn(sv.z, sv.w);
        }
        __syncthreads();

#pragma unroll 4
        for (int k = 0; k < 16; k++) {
            uint2 ra = *(const uint2*)&wsm[0][t][k * 4];
            uint2 rb = *(const uint2*)&wsm[1][t][k * 4];
            float2 a01 = __half22float2(*(__half2*)&ra.x);
            float2 a23 = __half22float2(*(__half2*)&ra.y);
            float2 b01 = __half22float2(*(__half2*)&rb.x);
            float2 b23 = __half22float2(*(__half2*)&rb.y);
#pragma unroll
            for (int n = 0; n < 16; n++) {
                float4 xv = xs4[n][kh * 16 + k];
                accP[n] += a01.x * xv.x + a01.y * xv.y + a23.x * xv.z + a23.y * xv.w;
                accS[n] += b01.x * xv.x + b01.y * xv.y + b23.x * xv.z + b23.y * xv.w;
            }
        }
    }

    float bv = bias[t];
#pragma unroll
    for (int n = 0; n < 16; n++) {
        g_proj16[(node0 + n) * FIN + t] = __float2half(accP[n]);
        out[(node0 + n) * FIN + t] = accS[n] + bv;   // skip + bias baseline
    }

    // ---- epilogue: per-(node,head) scores via 16-lane shuffle reduction ----
    float swv = sw_src[t], twv = sw_tgt[t];
    int h = t >> 4;
    bool leader = (t & 15) == 0;
    float msrc = -3.4e38f, mtgt = -3.4e38f;
#pragma unroll
    for (int n = 0; n < 16; n++) {
        float ps = accP[n] * swv;
        float pt = accP[n] * twv;
#pragma unroll
        for (int o = 8; o; o >>= 1) {
            ps += __shfl_down_sync(0xffffffffu, ps, o, 16);
            pt += __shfl_down_sync(0xffffffffu, pt, o, 16);
        }
        if (leader) {
            g_ssrc[(node0 + n) * NH + h] = ps;
            g_stgt[(node0 + n) * NH + h] = pt;
            msrc = fmaxf(msrc, ps);
            mtgt = fmaxf(mtgt, pt);
        }
    }
    if (leader) {
        atomicMax(&g_maxsrc[h], f2u_ord(msrc));
        atomicMax(&g_maxtgt[h], f2u_ord(mtgt));
    }
}

// ---------------- CSR scan: coalesced smem staging + warp-shuffle scan ---------
__global__ void __launch_bounds__(1024) k_scan() {
    const int PER = 10;                 // 1024 * 10 >= NN
    __shared__ int cs[NN];              // 40 KB, coalesced staging
    __shared__ int wt[32];
    int t = threadIdx.x;

    for (int i = t; i < NN; i += 1024) cs[i] = g_count[i];   // coalesced, MLP=10
    __syncthreads();

    int base = t * PER;
    int loc[PER];
    int sum = 0;
#pragma unroll
    for (int i = 0; i < PER; i++) {
        int idx = base + i;
        int v = (idx < NN) ? cs[idx] : 0;
        loc[i] = sum;
        sum += v;
    }
    int lane = t & 31, w = t >> 5;
    int s = sum;
#pragma unroll
    for (int o = 1; o < 32; o <<= 1) {
        int y = __shfl_up_sync(0xffffffffu, s, o);
        if (lane >= o) s += y;
    }
    if (lane == 31) wt[w] = s;
    __syncthreads();
    if (w == 0) {
        int v = wt[lane];
        int s2 = v;
#pragma unroll
        for (int o = 1; o < 32; o <<= 1) {
            int y = __shfl_up_sync(0xffffffffu, s2, o);
            if (lane >= o) s2 += y;
        }
        wt[lane] = s2 - v;
    }
    __syncthreads();
    int off = (s - sum) + wt[w];
#pragma unroll
    for (int i = 0; i < PER; i++) {
        int idx = base + i;
        if (idx < NN) cs[idx] = off + loc[i];
    }
    __syncthreads();
    for (int i = t; i < NN; i += 1024) {   // coalesced write-out
        int o = cs[i];
        g_offs[i] = o;
        g_cursor[i] = o;
    }
    if (t == 1023) g_offs[NN] = off + sum;

    // softmax shift constants (upper bound of edge max; shift-invariant)
    if (t < NH) {
        float c = u2f_ord(g_maxsrc[t]) + u2f_ord(g_maxtgt[t]);
        g_C[t] = fmaxf(c, NEG * c);
    }
}

// ---------------- CSR scatter: src ids into segment order ----------------
__global__ void k_scatter(const int* __restrict__ edges) {
    int e = blockIdx.x * 256 + threadIdx.x;
    if (e < EE) {
        int p = atomicAdd(&g_cursor[edges[EE + e]], 1);
        g_ssorted[p] = edges[e];
    }
}

// ---------------- aggregation: block per node, inline softmax, fp16 gather -----
// R14 structure, tile widened 32 -> 64 edges: halves barrier count per edge.
// Staging: 4 rounds x 128 threads cover 64 slots x 8 heads.
__global__ void __launch_bounds__(128) k_agg(float* __restrict__ out) {
    __shared__ int    src_s[64];
    __shared__ float  att_s[64][NH];
    __shared__ float4 red_s[4][32];
    __shared__ float  den_red[128];
    __shared__ float  stgt_s[NH], C_s[NH];

    int n = blockIdx.x, t = threadIdx.x;
    int lane = t & 31, w = t >> 5;

    if (t < NH) { stgt_s[t] = g_stgt[n * NH + t]; C_s[t] = g_C[t]; }
    if (t == 8) g_count[n] = 0;                  // re-zero for next replay
    if (n == 0 && t >= 16 && t < 24) g_maxsrc[t - 16] = 0u;
    if (n == 0 && t >= 24 && t < 32) g_maxtgt[t - 24] = 0u;
    __syncthreads();

    int start = g_offs[n], end = g_offs[n + 1];
    int hs = t & 7;                              // staging head
    float stgt_h = stgt_s[hs];
    float C_h = C_s[hs];
    float4 acc = make_float4(0.f, 0.f, 0.f, 0.f);
    float den_part = 0.f;
    int h4 = lane >> 2;                          // compute head (per feature group)

    for (int base = start; base < end; base += 64) {
        int m = min(64, end - base);
        __syncthreads();
        if (t < m) src_s[t] = g_ssorted[base + t];
        __syncthreads();
#pragma unroll
        for (int j = 0; j < 4; j++) {
            int slot = (t + j * 128) >> 3;
            if (slot < m) {
                float v = g_ssrc[src_s[slot] * NH + hs] + stgt_h;
                float ex = __expf(fmaxf(v, NEG * v) - C_h);
                att_s[slot][hs] = ex;
                den_part += ex;
            }
        }
        __syncthreads();
        int j = w;
        for (; j + 12 < m; j += 16) {            // 4 edges/iter -> MLP=4
            float a0 = att_s[j +  0][h4];
            float a1 = att_s[j +  4][h4];
            float a2 = att_s[j +  8][h4];
            float a3 = att_s[j + 12][h4];
            float2 r0 = ((const float2*)(g_proj16 + src_s[j +  0] * FIN))[lane];
            float2 r1 = ((const float2*)(g_proj16 + src_s[j +  4] * FIN))[lane];
            float2 r2 = ((const float2*)(g_proj16 + src_s[j +  8] * FIN))[lane];
            float2 r3 = ((const float2*)(g_proj16 + src_s[j + 12] * FIN))[lane];
            float2 f0a = __half22float2(*(__half2*)&r0.x), f0b = __half22float2(*(__half2*)&r0.y);
            float2 f1a = __half22float2(*(__half2*)&r1.x), f1b = __half22float2(*(__half2*)&r1.y);
            float2 f2a = __half22float2(*(__half2*)&r2.x), f2b = __half22float2(*(__half2*)&r2.y);
            float2 f3a = __half22float2(*(__half2*)&r3.x), f3b = __half22float2(*(__half2*)&r3.y);
            acc.x += a0 * f0a.x; acc.y += a0 * f0a.y; acc.z += a0 * f0b.x; acc.w += a0 * f0b.y;
            acc.x += a1 * f1a.x; acc.y += a1 * f1a.y; acc.z += a1 * f1b.x; acc.w += a1 * f1b.y;
            acc.x += a2 * f2a.x; acc.y += a2 * f2a.y; acc.z += a2 * f2b.x; acc.w += a2 * f2b.y;
            acc.x += a3 * f3a.x; acc.y += a3 * f3a.y; acc.z += a3 * f3b.x; acc.w += a3 * f3b.y;
        }
        for (; j < m; j += 4) {
            float a = att_s[j][h4];
            float2 r = ((const float2*)(g_proj16 + src_s[j] * FIN))[lane];
            float2 fa = __half22float2(*(__half2*)&r.x), fb = __half22float2(*(__half2*)&r.y);
            acc.x += a * fa.x; acc.y += a * fa.y; acc.z += a * fb.x; acc.w += a * fb.y;
        }
    }

    red_s[w][lane] = acc;
    den_red[t] = den_part;
    __syncthreads();
    if (w == 0) {
        float4 a = red_s[0][lane];
#pragma unroll
        for (int ww = 1; ww < 4; ww++) {
            float4 b = red_s[ww][lane];
            a.x += b.x; a.y += b.y; a.z += b.z; a.w += b.w;
        }
        float den = 0.f;
#pragma unroll
        for (int k = 0; k < 16; k++) den += den_red[h4 + k * 8];
        float inv = 1.0f / (den + EPSF);
        float4* o4 = (float4*)(out + n * FIN);
        float4 o = o4[lane];
        o.x += a.x * inv; o.y += a.y * inv; o.z += a.z * inv; o.w += a.w * inv;
        o4[lane] = o;
    }
}

// ---------------- launch ----------------
extern "C" void kernel_launch(void* const* d_in, const int* in_sizes, int n_in,
                              void* d_out, int out_size)
{
    const float* x     = (const float*)d_in[0];
    const int*   edges = (const int*)d_in[1];     // int32 (JAX x64 disabled)
    const float* Wp    = (const float*)d_in[2];
    const float* Ws    = (const float*)d_in[3];
    const float* s_src = (const float*)d_in[4];
    const float* s_tgt = (const float*)d_in[5];
    const float* bias  = (const float*)d_in[6];
    float* out = (float*)d_out;

    k_fused<<<GEMM_BLOCKS + COUNT_BLOCKS, 128>>>(x, Wp, Ws, bias, s_src, s_tgt, edges, out);
    k_scan<<<1, 1024>>>();
    k_scatter<<<(EE + 255) / 256, 256>>>(edges);
    k_agg<<<NN, 128>>>(out);
}